// round 14
// baseline (speedup 1.0000x reference)
#include <cuda_runtime.h>
#include <math.h>
#include <stdint.h>

#define FULLMASK 0xFFFFFFFFu
#define B_DIM 4
#define L_DIM 4096
#define A_DIM 96
#define KTOP  32

// ---------------- scratch ----------------
__device__ float d_v0[B_DIM * L_DIM];
__device__ float d_uq[B_DIM * 3 * L_DIM];
__device__ float d_uk[B_DIM * 3 * L_DIM];
__device__ float d_uks[B_DIM * 3 * L_DIM];
__device__ int   d_uki[B_DIM * 3 * L_DIM];
__device__ float d_rtau[B_DIM * L_DIM];
__device__ float d_v[B_DIM * 3 * L_DIM * 32];
__device__ float d_ctx[B_DIM * L_DIM * A_DIM];
__device__ float d_v2[B_DIM * L_DIM];
__device__ float d_wqe[3 * A_DIM];
__device__ float d_wke[3 * A_DIM];
__device__ float d_w2e[4 * A_DIM];
__device__ float d_b2po[1];
__device__ float d_WvT[A_DIM * A_DIM];
__device__ float d_WoutT[A_DIM * A_DIM];
__device__ float d_W1T[A_DIM * 4 * A_DIM];

#define DELTA_F (6.0f / 7.0f)
#define DE_F    (6.0f / 7.0f + 1e-6f)
#define RATIO_F (DELTA_F / DE_F)

// merge launch geometry
#define MBLK 98
#define QPB  42

__device__ __forceinline__ float wsum(float v) {
#pragma unroll
    for (int o = 16; o > 0; o >>= 1) v += __shfl_xor_sync(FULLMASK, v, o);
    return v;
}
__device__ __forceinline__ float wmax(float v) {
#pragma unroll
    for (int o = 16; o > 0; o >>= 1) v = fmaxf(v, __shfl_xor_sync(FULLMASK, v, o));
    return v;
}
__device__ __forceinline__ float wmin(float v) {
#pragma unroll
    for (int o = 16; o > 0; o >>= 1) v = fminf(v, __shfl_xor_sync(FULLMASK, v, o));
    return v;
}

__device__ __forceinline__ unsigned fmap(float f) {
    unsigned u = __float_as_uint(f);
    return u ^ ((u & 0x80000000u) ? 0xFFFFFFFFu : 0x80000000u);
}
__device__ __forceinline__ float funmap(unsigned x) {
    unsigned u = (x & 0x80000000u) ? (x ^ 0x80000000u) : ~x;
    return __uint_as_float(u);
}

// exact 8-hat spline (tau path only)
__device__ __forceinline__ float spline8(float u, const float* __restrict__ c) {
    float acc = 0.0f;
#pragma unroll
    for (int j = 0; j < 8; j++) {
        float ctr = -3.0f + (float)j * DELTA_F;
        float hat = fmaxf(1.0f - fabsf(u - ctr) * (1.0f / DE_F), 0.0f);
        acc = fmaf(hat, c[j], acc);
    }
    return acc;
}

// branchless 4-tap spline eval (exact; frontier init + fallback)
__device__ __forceinline__ float eval4(float bias, float ukv, const float* __restrict__ s_co, int lane) {
    const float OMR  = 1.0f - RATIO_F;
    const float TRM1 = 2.0f * RATIO_F - 1.0f;
    float s = bias - ukv * (7.0f / 6.0f);
    s = fminf(fmaxf(s, 1.5f), 13.5f);
    float fl = floorf(s); float fr = s - fl; int ii = (int)fl;
    float frR = fr * RATIO_F;
    float w0 = fmaxf(OMR - frR, 0.0f);
    float w1 = 1.0f - frR;
    float w2 = OMR + frR;
    float w3 = fmaxf(frR - TRM1, 0.0f);
    float c0 = s_co[(ii - 1) * 32 + lane], c1 = s_co[ii * 32 + lane];
    float c2 = s_co[(ii + 1) * 32 + lane], c3 = s_co[(ii + 2) * 32 + lane];
    return fmaf(w0, c0, fmaf(w1, c1, fmaf(w2, c2, w3 * c3)));
}

// ---------------- K1: v0 = x @ W_pre^T + b_pre, PLUS weight-prep blocks ----------------
__global__ void k1_pre(const float4* __restrict__ x4, const float4* __restrict__ W4,
                       const float* __restrict__ b_pre,
                       const float* __restrict__ Wq, const float* __restrict__ Wk,
                       const float* __restrict__ wq1, const float* __restrict__ wk1,
                       const float* __restrict__ W2, const float* __restrict__ w_po,
                       const float* __restrict__ b2, const float* __restrict__ Wout,
                       const float* __restrict__ W1, const float* __restrict__ Wv) {
    __shared__ float red[32 * 256];
    int t = threadIdx.x;

    if (blockIdx.x >= 512) {              // ---- prep blocks ----
        int pb = blockIdx.x - 512;        // 0..15
        if (pb == 0) {
            for (int idx = t; idx < 3 * A_DIM; idx += 256) {
                int h = idx / A_DIM, a = idx % A_DIM;
                float sq = 0.f, sk = 0.f;
                for (int d = 0; d < 32; d++) {
                    sq = fmaf(wq1[d], Wq[(h * 32 + d) * A_DIM + a], sq);
                    sk = fmaf(wk1[d], Wk[(h * 32 + d) * A_DIM + a], sk);
                }
                d_wqe[idx] = sq; d_wke[idx] = sk;
            }
            for (int j = t; j < 4 * A_DIM; j += 256) {
                float s = 0.f;
                for (int a = 0; a < A_DIM; a++) s = fmaf(W2[a * 4 * A_DIM + j], w_po[a], s);
                d_w2e[j] = s;
            }
            if (t == 0) {
                float s = 0.f;
                for (int a = 0; a < A_DIM; a++) s = fmaf(b2[a], w_po[a], s);
                d_b2po[0] = s;
            }
        } else if (pb == 1) {
            for (int idx = t; idx < A_DIM * A_DIM; idx += 256) {
                int r = idx / A_DIM, c = idx % A_DIM;
                d_WoutT[c * A_DIM + r] = Wout[r * A_DIM + c];
                d_WvT[c * A_DIM + r]   = Wv[r * A_DIM + c];
            }
        } else {
            for (int idx = (pb - 2) * 256 + t; idx < 4 * A_DIM * A_DIM; idx += 14 * 256) {
                int j = idx / A_DIM, a = idx % A_DIM;
                d_W1T[a * 4 * A_DIM + j] = W1[j * A_DIM + a];
            }
        }
        return;
    }

    int o0 = blockIdx.x * 8;
    float acc[8][4];
#pragma unroll
    for (int j = 0; j < 8; j++)
#pragma unroll
        for (int b = 0; b < 4; b++) acc[j][b] = 0.f;
#pragma unroll
    for (int m = 0; m < 4; m++) {
        int c = t + 256 * m;
        float4 xv[4];
#pragma unroll
        for (int b = 0; b < 4; b++) xv[b] = x4[b * 1024 + c];
#pragma unroll
        for (int j = 0; j < 8; j++) {
            float4 wv = W4[(size_t)(o0 + j) * 1024 + c];
#pragma unroll
            for (int b = 0; b < 4; b++) {
                acc[j][b] = fmaf(wv.x, xv[b].x, acc[j][b]);
                acc[j][b] = fmaf(wv.y, xv[b].y, acc[j][b]);
                acc[j][b] = fmaf(wv.z, xv[b].z, acc[j][b]);
                acc[j][b] = fmaf(wv.w, xv[b].w, acc[j][b]);
            }
        }
    }
#pragma unroll
    for (int j = 0; j < 8; j++)
#pragma unroll
        for (int b = 0; b < 4; b++) red[(j * 4 + b) * 256 + t] = acc[j][b];
    __syncthreads();
    int w = t >> 5, lane = t & 31;
    for (int r = w * 4; r < w * 4 + 4; r++) {
        float s = 0.f;
#pragma unroll
        for (int c = lane; c < 256; c += 32) s += red[r * 256 + c];
        s = wsum(s);
        if (lane == 0) {
            int j = r >> 2, b = r & 3;
            d_v0[b * L_DIM + o0 + j] = s + b_pre[o0 + j];
        }
    }
}

// ---------------- K2a: tok/LN1/uq/uk/tau only (no v) ----------------
__global__ void k2a_token(const float* __restrict__ w_emb, const float* __restrict__ b_emb,
                          const float* __restrict__ ln1g, const float* __restrict__ ln1b,
                          const float* __restrict__ tau_u, const float* __restrict__ tau_coeff) {
    int t = threadIdx.x, w = t >> 5, lane = t & 31;
    int tokbase = (blockIdx.x * 8 + w) * 4;
    int b = tokbase >> 12, l0 = tokbase & 4095;

    float we[3], be[3], g1[3], bb[3], tu[3], wq_[3][3], wk_[3][3];
#pragma unroll
    for (int m = 0; m < 3; m++) {
        int a = lane + 32 * m;
        we[m] = w_emb[a]; be[m] = b_emb[a];
        g1[m] = ln1g[a];  bb[m] = ln1b[a];
        tu[m] = tau_u[a];
#pragma unroll
        for (int h = 0; h < 3; h++) {
            wq_[h][m] = d_wqe[h * A_DIM + a];
            wk_[h][m] = d_wke[h * A_DIM + a];
        }
    }
    float h1v[4][3];
#pragma unroll
    for (int tt = 0; tt < 4; tt++) {
        float v0v = d_v0[tokbase + tt];
        float x0 = fmaf(v0v, we[0], be[0]);
        float x1 = fmaf(v0v, we[1], be[1]);
        float x2 = fmaf(v0v, we[2], be[2]);
        float s  = wsum(x0 + x1 + x2);
        float sq = wsum(x0 * x0 + x1 * x1 + x2 * x2);
        float mean = s * (1.0f / 96.0f);
        float var  = sq * (1.0f / 96.0f) - mean * mean;
        float rstd = rsqrtf(var + 1e-5f);
        h1v[tt][0] = fmaf((x0 - mean) * rstd, g1[0], bb[0]);
        h1v[tt][1] = fmaf((x1 - mean) * rstd, g1[1], bb[1]);
        h1v[tt][2] = fmaf((x2 - mean) * rstd, g1[2], bb[2]);
    }

    float pq[4][3], pk[4][3], pf[4];
#pragma unroll
    for (int tt = 0; tt < 4; tt++) {
        pf[tt] = 0.f;
#pragma unroll
        for (int h = 0; h < 3; h++) { pq[tt][h] = 0.f; pk[tt][h] = 0.f; }
#pragma unroll
        for (int m = 0; m < 3; m++) {
            float hv = h1v[tt][m];
#pragma unroll
            for (int h = 0; h < 3; h++) {
                pq[tt][h] = fmaf(hv, wq_[h][m], pq[tt][h]);
                pk[tt][h] = fmaf(hv, wk_[h][m], pk[tt][h]);
            }
            pf[tt] = fmaf(hv, tu[m], pf[tt]);
        }
    }
#pragma unroll
    for (int tt = 0; tt < 4; tt++) {
#pragma unroll
        for (int h = 0; h < 3; h++) { pq[tt][h] = wsum(pq[tt][h]); pk[tt][h] = wsum(pk[tt][h]); }
        pf[tt] = wsum(pf[tt]);
    }
    if (lane == 0) {
        float tc[8];
#pragma unroll
        for (int j = 0; j < 8; j++) tc[j] = tau_coeff[j];
#pragma unroll
        for (int tt = 0; tt < 4; tt++) {
            int l = l0 + tt;
            float fv = spline8(pf[tt], tc);
            float sp = fmaxf(fv, 0.0f) + log1pf(expf(-fabsf(fv)));
            d_rtau[b * L_DIM + l] = 1.0f / (sp + 0.05f + 1e-6f);
#pragma unroll
            for (int h = 0; h < 3; h++) {
                d_uq[(b * 3 + h) * L_DIM + l] = pq[tt][h];
                d_uk[(b * 3 + h) * L_DIM + l] = pk[tt][h];
            }
        }
    }
}

// ---------------- K2sv: fused  [blocks 0..11: sort uk]  [blocks 12..139: v GEMV] ----------------
__global__ void k2_sv(const float* __restrict__ w_emb, const float* __restrict__ b_emb,
                      const float* __restrict__ ln1g, const float* __restrict__ ln1b) {
    __shared__ __align__(16) float pool[12288];   // 48 KB, shared by both roles
    int t = threadIdx.x;

    if (blockIdx.x < 12) {
        // ---- bitonic sort of uk for this (b,h) ----
        unsigned long long* sk = (unsigned long long*)pool;
        int bh = blockIdx.x;
        for (int i = t; i < L_DIM; i += 1024) {
            float v = d_uk[bh * L_DIM + i];
            unsigned u = __float_as_uint(v);
            u ^= (u >> 31) ? 0xFFFFFFFFu : 0x80000000u;
            sk[i] = ((unsigned long long)u << 32) | (unsigned)i;
        }
        __syncthreads();
        for (int k = 2; k <= L_DIM; k <<= 1) {
            for (int j = k >> 1; j > 0; j >>= 1) {
                for (int i = t; i < L_DIM; i += 1024) {
                    int l = i ^ j;
                    if (l > i) {
                        bool asc = ((i & k) == 0);
                        unsigned long long a = sk[i], b = sk[l];
                        if ((a > b) == asc) { sk[i] = b; sk[l] = a; }
                    }
                }
                __syncthreads();
            }
        }
        for (int i = t; i < L_DIM; i += 1024) {
            int idx = (int)(sk[i] & 0xFFFFFFFFu);
            d_uki[bh * L_DIM + i] = idx;
            d_uks[bh * L_DIM + i] = d_uk[bh * L_DIM + idx];
        }
        return;
    }

    // ---- v = h1 @ Wv^T  (recompute h1; 32 warps/block, 4 tokens/warp) ----
    int w = t >> 5, lane = t & 31;
    int pb = blockIdx.x - 12;                     // 0..127
    int tokbase = (pb * 32 + w) * 4;
    int b = tokbase >> 12, l0 = tokbase & 4095;
    float (*sh)[4][A_DIM] = (float (*)[4][A_DIM])pool;

    float we[3], be[3], g1[3], bb[3];
#pragma unroll
    for (int m = 0; m < 3; m++) {
        int a = lane + 32 * m;
        we[m] = w_emb[a]; be[m] = b_emb[a];
        g1[m] = ln1g[a];  bb[m] = ln1b[a];
    }
#pragma unroll
    for (int tt = 0; tt < 4; tt++) {
        float v0v = d_v0[tokbase + tt];
        float x0 = fmaf(v0v, we[0], be[0]);
        float x1 = fmaf(v0v, we[1], be[1]);
        float x2 = fmaf(v0v, we[2], be[2]);
        float s  = wsum(x0 + x1 + x2);
        float sq = wsum(x0 * x0 + x1 * x1 + x2 * x2);
        float mean = s * (1.0f / 96.0f);
        float var  = sq * (1.0f / 96.0f) - mean * mean;
        float rstd = rsqrtf(var + 1e-5f);
        sh[w][tt][lane]      = fmaf((x0 - mean) * rstd, g1[0], bb[0]);
        sh[w][tt][lane + 32] = fmaf((x1 - mean) * rstd, g1[1], bb[1]);
        sh[w][tt][lane + 64] = fmaf((x2 - mean) * rstd, g1[2], bb[2]);
    }
    __syncwarp();

    float vacc[4][3];
#pragma unroll
    for (int tt = 0; tt < 4; tt++)
#pragma unroll
        for (int m = 0; m < 3; m++) vacc[tt][m] = 0.f;
    for (int i = 0; i < A_DIM; i++) {
        float wv0 = d_WvT[i * A_DIM + lane];
        float wv1 = d_WvT[i * A_DIM + lane + 32];
        float wv2 = d_WvT[i * A_DIM + lane + 64];
#pragma unroll
        for (int tt = 0; tt < 4; tt++) {
            float hv = sh[w][tt][i];
            vacc[tt][0] = fmaf(hv, wv0, vacc[tt][0]);
            vacc[tt][1] = fmaf(hv, wv1, vacc[tt][1]);
            vacc[tt][2] = fmaf(hv, wv2, vacc[tt][2]);
        }
    }
#pragma unroll
    for (int tt = 0; tt < 4; tt++) {
        int l = l0 + tt;
#pragma unroll
        for (int m = 0; m < 3; m++)
            d_v[(((size_t)(b * 3 + m)) * L_DIM + l) * 32 + lane] = vacc[tt][m];
    }
}

// ---------------- K3b: monotone-run merge top-32 ----------------
__global__ __launch_bounds__(256, 8) void k3_merge(const float* __restrict__ kcoeff) {
    __shared__ float s_uks[L_DIM];
    __shared__ unsigned short s_uki[L_DIM];
    __shared__ float s_co[16 * 32];
    __shared__ float s_p[24];
    __shared__ float s_slope[25];
    int bh = blockIdx.y;
    int b = bh / 3, h = bh - b * 3;
    int t = threadIdx.x, w = t >> 5, lane = t & 31;

    for (int i = t; i < L_DIM; i += 256) {
        s_uks[i] = d_uks[bh * L_DIM + i];
        s_uki[i] = (unsigned short)d_uki[bh * L_DIM + i];
    }
    for (int i = t; i < 512; i += 256) {
        int q = i >> 5;
        s_co[i] = (q >= 4 && q < 12) ? kcoeff[h * 8 + (q - 4)] : 0.0f;
    }
    if (t == 0) {
        float tmp[24]; int n = 0;
        for (int j = 0; j < 8; j++) {
            float c = -3.0f + (float)j * DELTA_F;
            tmp[n++] = c - DE_F; tmp[n++] = c; tmp[n++] = c + DE_F;
        }
        for (int i = 1; i < 24; i++) {
            float x = tmp[i]; int k2 = i - 1;
            while (k2 >= 0 && tmp[k2] > x) { tmp[k2 + 1] = tmp[k2]; k2--; }
            tmp[k2 + 1] = x;
        }
        for (int i = 0; i < 24; i++) s_p[i] = tmp[i];
    }
    __syncthreads();
    if (t < 25) {
        float dstar = (t == 0) ? s_p[0] - 1.0f : (t == 24 ? s_p[23] + 1.0f : 0.5f * (s_p[t - 1] + s_p[t]));
        float g = 0.f;
        for (int j = 0; j < 8; j++) {
            float c = -3.0f + (float)j * DELTA_F;
            float dd = dstar - c;
            if (fabsf(dd) < DE_F) g += copysignf(1.0f, dd) * kcoeff[h * 8 + j];
        }
        s_slope[t] = g * (1.0f / DE_F);
    }
    __syncthreads();

    const float* vp = d_v + (size_t)bh * L_DIM * 32;
    const float* gk = d_uk + bh * L_DIM;
    int q0 = blockIdx.x * QPB;

    for (int i = 0; ; i++) {
        int ql = w + 8 * i;
        if (ql >= QPB) break;
        int q = q0 + ql;
        if (q >= L_DIM) break;

        float uq = d_uq[bh * L_DIM + q];
        float bias = fmaf(uq, 7.0f / 6.0f, 7.5f);

        // --- partition ---
        int s = lane;
        float tb = uq - s_p[(s < 24) ? s : 23];
        int lo = 0, hi = L_DIM;
        while (hi > lo) { int mid = (lo + hi) >> 1; if (s_uks[mid] <= tb) lo = mid + 1; else hi = mid; }
        int ubv = (s < 24) ? lo : 0;
        int start = ubv;
        int endx = __shfl_up_sync(FULLMASK, ubv, 1);
        if (lane == 0) endx = L_DIM;

        // --- init frontier (linear per-segment model) ---
        int dir = 1, hpos = 0, hstop = 0, horig = 4095;
        float hv = -INFINITY, gseg = 0.f, Cc = 0.f;
        if (s < 25 && endx > start) {
            gseg = s_slope[s];
            dir  = (gseg > 0.f) ? -1 : 1;
            hpos  = (dir > 0) ? start : endx - 1;
            hstop = (dir > 0) ? endx  : start - 1;
            horig = (int)s_uki[hpos];
            float u0 = s_uks[hpos];
            hv = eval4(bias, u0, s_co, lane);
            Cc = fmaf(-gseg, u0, hv);
        }
        unsigned fo = fmap(hv);

        // --- 32 pops (ballot winner) + epilogue probe ---
        unsigned myvu = 0x80000000u; int myi = 0;
#pragma unroll 1
        for (int it = 0; it < 32; it++) {
            unsigned vmx = __reduce_max_sync(FULLMASK, fo);
            unsigned wb = __ballot_sync(FULLMASK, fo == vmx);
            int wl = __ffs(wb) - 1;
            int wi = __shfl_sync(FULLMASK, horig, wl);
            if (lane == it) { myvu = vmx; myi = wi; }
            if (lane == wl) {
                hpos += dir;
                if (hpos == hstop) { hv = -INFINITY; }
                else { horig = (int)s_uki[hpos]; hv = fmaf(gseg, s_uks[hpos], Cc); }
                fo = fmap(hv);
            }
        }
        unsigned wv33u = __reduce_max_sync(FULLMASK, fo);
        float myv = funmap(myvu);

        unsigned minvu = __shfl_sync(FULLMASK, myvu, 31);
        if (wv33u == minvu) {
            float minv = funmap(minvu);
            if (minv == 0.0f) {
                // tie among exact zeros: keep positives (lanes 0..c-1), refill with
                // smallest original indices among out-of-support keys.
                unsigned posmask = __ballot_sync(FULLMASK, myv > 0.0f);
                int c = __popc(posmask);
                float tbp = uq - s_p[23];
                float tbs = uq - s_p[0];
                int remaining = 32 - c, taken = 0, base = 0;
                while (remaining > 0 && base < L_DIM) {
                    float ukv = __ldg(gk + base + lane);
                    bool outw = (ukv <= tbp) || !(ukv <= tbs);
                    unsigned mask = __ballot_sync(FULLMASK, outw);
                    int cnt = __popc(mask);
                    int take = (cnt < remaining) ? cnt : remaining;
                    int slotpos = lane - (c + taken);
                    if (slotpos >= 0 && slotpos < take) {
                        int bitpos = (int)__fns(mask, 0, slotpos + 1);
                        myv = 0.0f; myi = base + bitpos;
                    }
                    taken += take; remaining -= take; base += 32;
                }
            } else {
                // nonzero boundary tie: exact streaming fallback
                float bestv; int besti; float curmin;
                {
                    bestv = eval4(bias, __ldg(gk + lane), s_co, lane);
                    besti = lane;
                    curmin = wmin(bestv);
                }
                for (int step = 1; step < 128; step++) {
                    int j = step * 32 + lane;
                    float cand = eval4(bias, __ldg(gk + j), s_co, lane);
                    unsigned mm = __ballot_sync(FULLMASK, cand > curmin);
                    while (mm) {
                        int src = __ffs(mm) - 1; mm &= mm - 1;
                        float cv = __shfl_sync(FULLMASK, cand, src);
                        if (cv > curmin) {
                            int cj = step * 32 + src;
                            float mv = bestv; int mi = besti; int ml = lane;
#pragma unroll
                            for (int off = 16; off > 0; off >>= 1) {
                                float ov = __shfl_xor_sync(FULLMASK, mv, off);
                                int oi = __shfl_xor_sync(FULLMASK, mi, off);
                                int ol = __shfl_xor_sync(FULLMASK, ml, off);
                                if (ov < mv || (ov == mv && oi > mi)) { mv = ov; mi = oi; ml = ol; }
                            }
                            if (lane == ml) { bestv = cv; besti = cj; }
                            curmin = wmin(bestv);
                        }
                    }
                }
                myv = bestv; myi = besti;
            }
        }

        // --- softmax + gather ---
        float rtau = d_rtau[b * L_DIM + q];
        float tv = myv * rtau;
        float mx = wmax(tv);
        float e = expf(tv - mx);
        float se = wsum(e);
        float acc = 0.f;
#pragma unroll
        for (int k2 = 0; k2 < 32; k2++) {
            float ev = __shfl_sync(FULLMASK, e, k2);
            int ji = __shfl_sync(FULLMASK, myi, k2);
            acc = fmaf(ev, vp[(size_t)ji * 32 + lane], acc);
        }
        d_ctx[((size_t)b * L_DIM + q) * A_DIM + h * 32 + lane] = acc * (1.0f / se);
    }
}

// ---------------- K4: attn_out + LN2 + FFN -> v2 ----------------
__global__ void k4_ffn(const float* __restrict__ w_emb, const float* __restrict__ b_emb,
                       const float* __restrict__ ln2g, const float* __restrict__ ln2b,
                       const float* __restrict__ b1, const float* __restrict__ w_po,
                       const float* __restrict__ bpo) {
    __shared__ float sctx[8][4][A_DIM];
    __shared__ float sh2[8][4][A_DIM];
    int t = threadIdx.x, w = t >> 5, lane = t & 31;
    int tokbase = (blockIdx.x * 8 + w) * 4;

#pragma unroll
    for (int tt = 0; tt < 4; tt++)
#pragma unroll
        for (int m = 0; m < 3; m++)
            sctx[w][tt][lane + 32 * m] = d_ctx[(size_t)(tokbase + tt) * A_DIM + lane + 32 * m];
    __syncwarp();

    float ao[4][3];
#pragma unroll
    for (int tt = 0; tt < 4; tt++)
#pragma unroll
        for (int m = 0; m < 3; m++) ao[tt][m] = 0.f;
    for (int i = 0; i < A_DIM; i++) {
        float w0 = d_WoutT[i * A_DIM + lane];
        float w1 = d_WoutT[i * A_DIM + lane + 32];
        float w2 = d_WoutT[i * A_DIM + lane + 64];
#pragma unroll
        for (int tt = 0; tt < 4; tt++) {
            float cv = sctx[w][tt][i];
            ao[tt][0] = fmaf(cv, w0, ao[tt][0]);
            ao[tt][1] = fmaf(cv, w1, ao[tt][1]);
            ao[tt][2] = fmaf(cv, w2, ao[tt][2]);
        }
    }
    float we[3], be[3], g2[3], b2v[3], wp[3];
#pragma unroll
    for (int m = 0; m < 3; m++) {
        int a = lane + 32 * m;
        we[m] = w_emb[a]; be[m] = b_emb[a];
        g2[m] = ln2g[a];  b2v[m] = ln2b[a]; wp[m] = w_po[a];
    }
    float v2acc[4];
#pragma unroll
    for (int tt = 0; tt < 4; tt++) {
        float v0v = d_v0[tokbase + tt];
        float y0 = fmaf(v0v, we[0], be[0]) + ao[tt][0];
        float y1 = fmaf(v0v, we[1], be[1]) + ao[tt][1];
        float y2 = fmaf(v0v, we[2], be[2]) + ao[tt][2];
        v2acc[tt] = wsum(y0 * wp[0] + y1 * wp[1] + y2 * wp[2]);
        float s  = wsum(y0 + y1 + y2);
        float sq = wsum(y0 * y0 + y1 * y1 + y2 * y2);
        float mean = s * (1.0f / 96.0f);
        float var  = sq * (1.0f / 96.0f) - mean * mean;
        float rstd = rsqrtf(var + 1e-5f);
        sh2[w][tt][lane]      = fmaf((y0 - mean) * rstd, g2[0], b2v[0]);
        sh2[w][tt][lane + 32] = fmaf((y1 - mean) * rstd, g2[1], b2v[1]);
        sh2[w][tt][lane + 64] = fmaf((y2 - mean) * rstd, g2[2], b2v[2]);
    }
    __syncwarp();

    float acc[4][12];
#pragma unroll
    for (int tt = 0; tt < 4; tt++)
#pragma unroll
        for (int m = 0; m < 12; m++) acc[tt][m] = 0.f;
    for (int a = 0; a < A_DIM; a++) {
        float wv[12];
#pragma unroll
        for (int m = 0; m < 12; m++) wv[m] = d_W1T[a * 384 + lane + 32 * m];
#pragma unroll
        for (int tt = 0; tt < 4; tt++) {
            float hv = sh2[w][tt][a];
#pragma unroll
            for (int m = 0; m < 12; m++) acc[tt][m] = fmaf(hv, wv[m], acc[tt][m]);
        }
    }
    float b1v[12], w2v[12];
#pragma unroll
    for (int m = 0; m < 12; m++) {
        b1v[m] = b1[lane + 32 * m];
        w2v[m] = d_w2e[lane + 32 * m];
    }
    float bpo_v = bpo[0] + d_b2po[0];
#pragma unroll
    for (int tt = 0; tt < 4; tt++) {
        float fp = 0.f;
#pragma unroll
        for (int m = 0; m < 12; m++) {
            float xg = acc[tt][m] + b1v[m];
            float g = 0.5f * xg * (1.0f + erff(xg * 0.70710678118654752f));
            fp = fmaf(g, w2v[m], fp);
        }
        fp = wsum(fp);
        if (lane == 0) d_v2[tokbase + tt] = v2acc[tt] + bpo_v + fp;
    }
}

// ---------------- K5: out = LN(x + v2) over 4096 ----------------
__global__ void k5_final(const float* __restrict__ x, const float* __restrict__ lg,
                         const float* __restrict__ lb, float* __restrict__ out) {
    __shared__ float s_s[32], s_q[32];
    int b = blockIdx.x, t = threadIdx.x;
    float vals[4];
    float s = 0.f, sq = 0.f;
#pragma unroll
    for (int m = 0; m < 4; m++) {
        int i = t + 1024 * m;
        float v = x[b * L_DIM + i] + d_v2[b * L_DIM + i];
        vals[m] = v; s += v; sq += v * v;
    }
    s = wsum(s); sq = wsum(sq);
    int w = t >> 5, lane = t & 31;
    if (lane == 0) { s_s[w] = s; s_q[w] = sq; }
    __syncthreads();
    if (w == 0) {
        float a = s_s[lane], c = s_q[lane];
        a = wsum(a); c = wsum(c);
        if (lane == 0) { s_s[0] = a; s_q[0] = c; }
    }
    __syncthreads();
    float mean = s_s[0] * (1.0f / 4096.0f);
    float var  = s_q[0] * (1.0f / 4096.0f) - mean * mean;
    float rstd = rsqrtf(var + 1e-5f);
#pragma unroll
    for (int m = 0; m < 4; m++) {
        int i = t + 1024 * m;
        out[b * L_DIM + i] = fmaf((vals[m] - mean) * rstd, lg[i], lb[i]);
    }
}

extern "C" void kernel_launch(void* const* d_in, const int* in_sizes, int n_in,
                              void* d_out, int out_size) {
    const float* x       = (const float*)d_in[0];
    const float* W_pre   = (const float*)d_in[1];
    const float* b_pre   = (const float*)d_in[2];
    const float* w_emb   = (const float*)d_in[3];
    const float* b_emb   = (const float*)d_in[4];
    const float* ln1_g   = (const float*)d_in[5];
    const float* ln1_b   = (const float*)d_in[6];
    const float* Wq      = (const float*)d_in[7];
    const float* Wk      = (const float*)d_in[8];
    const float* Wv      = (const float*)d_in[9];
    const float* wq1     = (const float*)d_in[10];
    const float* wk1     = (const float*)d_in[11];
    const float* kcoeff  = (const float*)d_in[12];
    const float* tau_u   = (const float*)d_in[13];
    const float* tau_co  = (const float*)d_in[14];
    const float* Wout    = (const float*)d_in[15];
    const float* ln2_g   = (const float*)d_in[16];
    const float* ln2_b   = (const float*)d_in[17];
    const float* ffn_w1  = (const float*)d_in[18];
    const float* ffn_b1  = (const float*)d_in[19];
    const float* ffn_w2  = (const float*)d_in[20];
    const float* ffn_b2  = (const float*)d_in[21];
    const float* w_po    = (const float*)d_in[22];
    const float* b_po    = (const float*)d_in[23];
    const float* lnf_g   = (const float*)d_in[24];
    const float* lnf_b   = (const float*)d_in[25];
    float* out = (float*)d_out;

    k1_pre<<<528, 256>>>((const float4*)x, (const float4*)W_pre, b_pre,
                         Wq, Wk, wq1, wk1, ffn_w2, w_po, ffn_b2, Wout, ffn_w1, Wv);
    k2a_token<<<512, 256>>>(w_emb, b_emb, ln1_g, ln1_b, tau_u, tau_co);
    k2_sv<<<140, 1024>>>(w_emb, b_emb, ln1_g, ln1_b);       // sort (12 blks) + v GEMV (128 blks)
    k3_merge<<<dim3(MBLK, 12), 256>>>(kcoeff);
    k4_ffn<<<512, 256>>>(w_emb, b_emb, ln2_g, ln2_b, ffn_b1, w_po, b_po);
    k5_final<<<4, 1024>>>(x, lnf_g, lnf_b, out);
}

// round 15
// speedup vs baseline: 1.0052x; 1.0052x over previous
#include <cuda_runtime.h>
#include <math.h>
#include <stdint.h>

#define FULLMASK 0xFFFFFFFFu
#define B_DIM 4
#define L_DIM 4096
#define A_DIM 96
#define KTOP  32

// ---------------- scratch ----------------
__device__ float d_v0[B_DIM * L_DIM];
__device__ float d_uq[B_DIM * 3 * L_DIM];
__device__ float d_uk[B_DIM * 3 * L_DIM];
__device__ float d_uks[B_DIM * 3 * L_DIM];
__device__ int   d_uki[B_DIM * 3 * L_DIM];
__device__ float d_rtau[B_DIM * L_DIM];
__device__ float d_v[B_DIM * 3 * L_DIM * 32];
__device__ float d_ctx[B_DIM * L_DIM * A_DIM];
__device__ float d_v2[B_DIM * L_DIM];
__device__ float d_wqe[3 * A_DIM];
__device__ float d_wke[3 * A_DIM];
__device__ float d_w2e[4 * A_DIM];
__device__ float d_b2po[1];
__device__ float d_WvT[A_DIM * A_DIM];
__device__ float d_WoutT[A_DIM * A_DIM];
__device__ float d_W1T[A_DIM * 4 * A_DIM];

#define DELTA_F (6.0f / 7.0f)
#define DE_F    (6.0f / 7.0f + 1e-6f)
#define RATIO_F (DELTA_F / DE_F)

// merge launch geometry
#define MBLK 98
#define QPB  42

__device__ __forceinline__ float wsum(float v) {
#pragma unroll
    for (int o = 16; o > 0; o >>= 1) v += __shfl_xor_sync(FULLMASK, v, o);
    return v;
}
__device__ __forceinline__ float wmax(float v) {
#pragma unroll
    for (int o = 16; o > 0; o >>= 1) v = fmaxf(v, __shfl_xor_sync(FULLMASK, v, o));
    return v;
}
__device__ __forceinline__ float wmin(float v) {
#pragma unroll
    for (int o = 16; o > 0; o >>= 1) v = fminf(v, __shfl_xor_sync(FULLMASK, v, o));
    return v;
}

__device__ __forceinline__ unsigned fmap(float f) {
    unsigned u = __float_as_uint(f);
    return u ^ ((u & 0x80000000u) ? 0xFFFFFFFFu : 0x80000000u);
}
__device__ __forceinline__ float funmap(unsigned x) {
    unsigned u = (x & 0x80000000u) ? (x ^ 0x80000000u) : ~x;
    return __uint_as_float(u);
}

// exact 8-hat spline (tau path only)
__device__ __forceinline__ float spline8(float u, const float* __restrict__ c) {
    float acc = 0.0f;
#pragma unroll
    for (int j = 0; j < 8; j++) {
        float ctr = -3.0f + (float)j * DELTA_F;
        float hat = fmaxf(1.0f - fabsf(u - ctr) * (1.0f / DE_F), 0.0f);
        acc = fmaf(hat, c[j], acc);
    }
    return acc;
}

// branchless 4-tap spline eval (exact; frontier init + fallback)
__device__ __forceinline__ float eval4(float bias, float ukv, const float* __restrict__ s_co, int lane) {
    const float OMR  = 1.0f - RATIO_F;
    const float TRM1 = 2.0f * RATIO_F - 1.0f;
    float s = bias - ukv * (7.0f / 6.0f);
    s = fminf(fmaxf(s, 1.5f), 13.5f);
    float fl = floorf(s); float fr = s - fl; int ii = (int)fl;
    float frR = fr * RATIO_F;
    float w0 = fmaxf(OMR - frR, 0.0f);
    float w1 = 1.0f - frR;
    float w2 = OMR + frR;
    float w3 = fmaxf(frR - TRM1, 0.0f);
    float c0 = s_co[(ii - 1) * 32 + lane], c1 = s_co[ii * 32 + lane];
    float c2 = s_co[(ii + 1) * 32 + lane], c3 = s_co[(ii + 2) * 32 + lane];
    return fmaf(w0, c0, fmaf(w1, c1, fmaf(w2, c2, w3 * c3)));
}

// ---------------- K1: v0 = x @ W_pre^T + b_pre, PLUS weight-prep blocks ----------------
__global__ void k1_pre(const float4* __restrict__ x4, const float4* __restrict__ W4,
                       const float* __restrict__ b_pre,
                       const float* __restrict__ Wq, const float* __restrict__ Wk,
                       const float* __restrict__ wq1, const float* __restrict__ wk1,
                       const float* __restrict__ W2, const float* __restrict__ w_po,
                       const float* __restrict__ b2, const float* __restrict__ Wout,
                       const float* __restrict__ W1, const float* __restrict__ Wv) {
    __shared__ float red[32 * 256];
    int t = threadIdx.x;

    if (blockIdx.x >= 512) {              // ---- prep blocks ----
        int pb = blockIdx.x - 512;        // 0..15
        if (pb == 0) {
            for (int idx = t; idx < 3 * A_DIM; idx += 256) {
                int h = idx / A_DIM, a = idx % A_DIM;
                float sq = 0.f, sk = 0.f;
                for (int d = 0; d < 32; d++) {
                    sq = fmaf(wq1[d], Wq[(h * 32 + d) * A_DIM + a], sq);
                    sk = fmaf(wk1[d], Wk[(h * 32 + d) * A_DIM + a], sk);
                }
                d_wqe[idx] = sq; d_wke[idx] = sk;
            }
            for (int j = t; j < 4 * A_DIM; j += 256) {
                float s = 0.f;
                for (int a = 0; a < A_DIM; a++) s = fmaf(W2[a * 4 * A_DIM + j], w_po[a], s);
                d_w2e[j] = s;
            }
            if (t == 0) {
                float s = 0.f;
                for (int a = 0; a < A_DIM; a++) s = fmaf(b2[a], w_po[a], s);
                d_b2po[0] = s;
            }
        } else if (pb == 1) {
            for (int idx = t; idx < A_DIM * A_DIM; idx += 256) {
                int r = idx / A_DIM, c = idx % A_DIM;
                d_WoutT[c * A_DIM + r] = Wout[r * A_DIM + c];
                d_WvT[c * A_DIM + r]   = Wv[r * A_DIM + c];
            }
        } else {
            for (int idx = (pb - 2) * 256 + t; idx < 4 * A_DIM * A_DIM; idx += 14 * 256) {
                int j = idx / A_DIM, a = idx % A_DIM;
                d_W1T[a * 4 * A_DIM + j] = W1[j * A_DIM + a];
            }
        }
        return;
    }

    int o0 = blockIdx.x * 8;
    float acc[8][4];
#pragma unroll
    for (int j = 0; j < 8; j++)
#pragma unroll
        for (int b = 0; b < 4; b++) acc[j][b] = 0.f;
#pragma unroll
    for (int m = 0; m < 4; m++) {
        int c = t + 256 * m;
        float4 xv[4];
#pragma unroll
        for (int b = 0; b < 4; b++) xv[b] = x4[b * 1024 + c];
#pragma unroll
        for (int j = 0; j < 8; j++) {
            float4 wv = W4[(size_t)(o0 + j) * 1024 + c];
#pragma unroll
            for (int b = 0; b < 4; b++) {
                acc[j][b] = fmaf(wv.x, xv[b].x, acc[j][b]);
                acc[j][b] = fmaf(wv.y, xv[b].y, acc[j][b]);
                acc[j][b] = fmaf(wv.z, xv[b].z, acc[j][b]);
                acc[j][b] = fmaf(wv.w, xv[b].w, acc[j][b]);
            }
        }
    }
#pragma unroll
    for (int j = 0; j < 8; j++)
#pragma unroll
        for (int b = 0; b < 4; b++) red[(j * 4 + b) * 256 + t] = acc[j][b];
    __syncthreads();
    int w = t >> 5, lane = t & 31;
    for (int r = w * 4; r < w * 4 + 4; r++) {
        float s = 0.f;
#pragma unroll
        for (int c = lane; c < 256; c += 32) s += red[r * 256 + c];
        s = wsum(s);
        if (lane == 0) {
            int j = r >> 2, b = r & 3;
            d_v0[b * L_DIM + o0 + j] = s + b_pre[o0 + j];
        }
    }
}

// ---------------- K2a: tok/LN1/uq/uk/tau only (no v) ----------------
__global__ void k2a_token(const float* __restrict__ w_emb, const float* __restrict__ b_emb,
                          const float* __restrict__ ln1g, const float* __restrict__ ln1b,
                          const float* __restrict__ tau_u, const float* __restrict__ tau_coeff) {
    int t = threadIdx.x, w = t >> 5, lane = t & 31;
    int tokbase = (blockIdx.x * 8 + w) * 4;
    int b = tokbase >> 12, l0 = tokbase & 4095;

    float we[3], be[3], g1[3], bb[3], tu[3], wq_[3][3], wk_[3][3];
#pragma unroll
    for (int m = 0; m < 3; m++) {
        int a = lane + 32 * m;
        we[m] = w_emb[a]; be[m] = b_emb[a];
        g1[m] = ln1g[a];  bb[m] = ln1b[a];
        tu[m] = tau_u[a];
#pragma unroll
        for (int h = 0; h < 3; h++) {
            wq_[h][m] = d_wqe[h * A_DIM + a];
            wk_[h][m] = d_wke[h * A_DIM + a];
        }
    }
    float h1v[4][3];
#pragma unroll
    for (int tt = 0; tt < 4; tt++) {
        float v0v = d_v0[tokbase + tt];
        float x0 = fmaf(v0v, we[0], be[0]);
        float x1 = fmaf(v0v, we[1], be[1]);
        float x2 = fmaf(v0v, we[2], be[2]);
        float s  = wsum(x0 + x1 + x2);
        float sq = wsum(x0 * x0 + x1 * x1 + x2 * x2);
        float mean = s * (1.0f / 96.0f);
        float var  = sq * (1.0f / 96.0f) - mean * mean;
        float rstd = rsqrtf(var + 1e-5f);
        h1v[tt][0] = fmaf((x0 - mean) * rstd, g1[0], bb[0]);
        h1v[tt][1] = fmaf((x1 - mean) * rstd, g1[1], bb[1]);
        h1v[tt][2] = fmaf((x2 - mean) * rstd, g1[2], bb[2]);
    }

    float pq[4][3], pk[4][3], pf[4];
#pragma unroll
    for (int tt = 0; tt < 4; tt++) {
        pf[tt] = 0.f;
#pragma unroll
        for (int h = 0; h < 3; h++) { pq[tt][h] = 0.f; pk[tt][h] = 0.f; }
#pragma unroll
        for (int m = 0; m < 3; m++) {
            float hv = h1v[tt][m];
#pragma unroll
            for (int h = 0; h < 3; h++) {
                pq[tt][h] = fmaf(hv, wq_[h][m], pq[tt][h]);
                pk[tt][h] = fmaf(hv, wk_[h][m], pk[tt][h]);
            }
            pf[tt] = fmaf(hv, tu[m], pf[tt]);
        }
    }
#pragma unroll
    for (int tt = 0; tt < 4; tt++) {
#pragma unroll
        for (int h = 0; h < 3; h++) { pq[tt][h] = wsum(pq[tt][h]); pk[tt][h] = wsum(pk[tt][h]); }
        pf[tt] = wsum(pf[tt]);
    }
    if (lane == 0) {
        float tc[8];
#pragma unroll
        for (int j = 0; j < 8; j++) tc[j] = tau_coeff[j];
#pragma unroll
        for (int tt = 0; tt < 4; tt++) {
            int l = l0 + tt;
            float fv = spline8(pf[tt], tc);
            float sp = fmaxf(fv, 0.0f) + log1pf(expf(-fabsf(fv)));
            d_rtau[b * L_DIM + l] = 1.0f / (sp + 0.05f + 1e-6f);
#pragma unroll
            for (int h = 0; h < 3; h++) {
                d_uq[(b * 3 + h) * L_DIM + l] = pq[tt][h];
                d_uk[(b * 3 + h) * L_DIM + l] = pk[tt][h];
            }
        }
    }
}

// ---------------- K2sv: fused  [blocks 0..11: sort uk]  [blocks 12..139: v GEMV] ----------------
__global__ void k2_sv(const float* __restrict__ w_emb, const float* __restrict__ b_emb,
                      const float* __restrict__ ln1g, const float* __restrict__ ln1b) {
    __shared__ __align__(16) float pool[12288];   // 48 KB, shared by both roles
    int t = threadIdx.x;

    if (blockIdx.x < 12) {
        unsigned long long* sk = (unsigned long long*)pool;
        int bh = blockIdx.x;
        for (int i = t; i < L_DIM; i += 1024) {
            float v = d_uk[bh * L_DIM + i];
            unsigned u = __float_as_uint(v);
            u ^= (u >> 31) ? 0xFFFFFFFFu : 0x80000000u;
            sk[i] = ((unsigned long long)u << 32) | (unsigned)i;
        }
        __syncthreads();
        for (int k = 2; k <= L_DIM; k <<= 1) {
            for (int j = k >> 1; j > 0; j >>= 1) {
                for (int i = t; i < L_DIM; i += 1024) {
                    int l = i ^ j;
                    if (l > i) {
                        bool asc = ((i & k) == 0);
                        unsigned long long a = sk[i], b = sk[l];
                        if ((a > b) == asc) { sk[i] = b; sk[l] = a; }
                    }
                }
                __syncthreads();
            }
        }
        for (int i = t; i < L_DIM; i += 1024) {
            int idx = (int)(sk[i] & 0xFFFFFFFFu);
            d_uki[bh * L_DIM + i] = idx;
            d_uks[bh * L_DIM + i] = d_uk[bh * L_DIM + idx];
        }
        return;
    }

    // ---- v = h1 @ Wv^T ----
    int w = t >> 5, lane = t & 31;
    int pb = blockIdx.x - 12;
    int tokbase = (pb * 32 + w) * 4;
    int b = tokbase >> 12, l0 = tokbase & 4095;
    float (*sh)[4][A_DIM] = (float (*)[4][A_DIM])pool;

    float we[3], be[3], g1[3], bb[3];
#pragma unroll
    for (int m = 0; m < 3; m++) {
        int a = lane + 32 * m;
        we[m] = w_emb[a]; be[m] = b_emb[a];
        g1[m] = ln1g[a];  bb[m] = ln1b[a];
    }
#pragma unroll
    for (int tt = 0; tt < 4; tt++) {
        float v0v = d_v0[tokbase + tt];
        float x0 = fmaf(v0v, we[0], be[0]);
        float x1 = fmaf(v0v, we[1], be[1]);
        float x2 = fmaf(v0v, we[2], be[2]);
        float s  = wsum(x0 + x1 + x2);
        float sq = wsum(x0 * x0 + x1 * x1 + x2 * x2);
        float mean = s * (1.0f / 96.0f);
        float var  = sq * (1.0f / 96.0f) - mean * mean;
        float rstd = rsqrtf(var + 1e-5f);
        sh[w][tt][lane]      = fmaf((x0 - mean) * rstd, g1[0], bb[0]);
        sh[w][tt][lane + 32] = fmaf((x1 - mean) * rstd, g1[1], bb[1]);
        sh[w][tt][lane + 64] = fmaf((x2 - mean) * rstd, g1[2], bb[2]);
    }
    __syncwarp();

    float vacc[4][3];
#pragma unroll
    for (int tt = 0; tt < 4; tt++)
#pragma unroll
        for (int m = 0; m < 3; m++) vacc[tt][m] = 0.f;
    for (int i = 0; i < A_DIM; i++) {
        float wv0 = d_WvT[i * A_DIM + lane];
        float wv1 = d_WvT[i * A_DIM + lane + 32];
        float wv2 = d_WvT[i * A_DIM + lane + 64];
#pragma unroll
        for (int tt = 0; tt < 4; tt++) {
            float hv = sh[w][tt][i];
            vacc[tt][0] = fmaf(hv, wv0, vacc[tt][0]);
            vacc[tt][1] = fmaf(hv, wv1, vacc[tt][1]);
            vacc[tt][2] = fmaf(hv, wv2, vacc[tt][2]);
        }
    }
#pragma unroll
    for (int tt = 0; tt < 4; tt++) {
        int l = l0 + tt;
#pragma unroll
        for (int m = 0; m < 3; m++)
            d_v[(((size_t)(b * 3 + m)) * L_DIM + l) * 32 + lane] = vacc[tt][m];
    }
}

// ---------------- K3b: monotone-run merge top-32 (REDUX-only winner, 8 blocks/SM) ----------------
__global__ __launch_bounds__(256, 8) void k3_merge(const float* __restrict__ kcoeff) {
    __shared__ float s_uks[L_DIM];
    __shared__ unsigned short s_uki[L_DIM];
    __shared__ float s_co[16 * 32];
    __shared__ float s_p[24];
    __shared__ float s_slope[25];
    int bh = blockIdx.y;
    int b = bh / 3, h = bh - b * 3;
    int t = threadIdx.x, w = t >> 5, lane = t & 31;

    for (int i = t; i < L_DIM; i += 256) {
        s_uks[i] = d_uks[bh * L_DIM + i];
        s_uki[i] = (unsigned short)d_uki[bh * L_DIM + i];
    }
    for (int i = t; i < 512; i += 256) {
        int q = i >> 5;
        s_co[i] = (q >= 4 && q < 12) ? kcoeff[h * 8 + (q - 4)] : 0.0f;
    }
    if (t == 0) {
        float tmp[24]; int n = 0;
        for (int j = 0; j < 8; j++) {
            float c = -3.0f + (float)j * DELTA_F;
            tmp[n++] = c - DE_F; tmp[n++] = c; tmp[n++] = c + DE_F;
        }
        for (int i = 1; i < 24; i++) {
            float x = tmp[i]; int k2 = i - 1;
            while (k2 >= 0 && tmp[k2] > x) { tmp[k2 + 1] = tmp[k2]; k2--; }
            tmp[k2 + 1] = x;
        }
        for (int i = 0; i < 24; i++) s_p[i] = tmp[i];
    }
    __syncthreads();
    if (t < 25) {
        float dstar = (t == 0) ? s_p[0] - 1.0f : (t == 24 ? s_p[23] + 1.0f : 0.5f * (s_p[t - 1] + s_p[t]));
        float g = 0.f;
        for (int j = 0; j < 8; j++) {
            float c = -3.0f + (float)j * DELTA_F;
            float dd = dstar - c;
            if (fabsf(dd) < DE_F) g += copysignf(1.0f, dd) * kcoeff[h * 8 + j];
        }
        s_slope[t] = g * (1.0f / DE_F);
    }
    __syncthreads();

    const float* vp = d_v + (size_t)bh * L_DIM * 32;
    const float* gk = d_uk + bh * L_DIM;
    int q0 = blockIdx.x * QPB;

    for (int i = 0; ; i++) {
        int ql = w + 8 * i;
        if (ql >= QPB) break;
        int q = q0 + ql;
        if (q >= L_DIM) break;

        float uq = d_uq[bh * L_DIM + q];
        float bias = fmaf(uq, 7.0f / 6.0f, 7.5f);

        // --- partition ---
        int s = lane;
        float tb = uq - s_p[(s < 24) ? s : 23];
        int lo = 0, hi = L_DIM;
        while (hi > lo) { int mid = (lo + hi) >> 1; if (s_uks[mid] <= tb) lo = mid + 1; else hi = mid; }
        int ubv = (s < 24) ? lo : 0;
        int start = ubv;
        int endx = __shfl_up_sync(FULLMASK, ubv, 1);
        if (lane == 0) endx = L_DIM;

        // --- init frontier (linear per-segment model) ---
        int dir = 1, hpos = 0, hstop = 0, horig = 4095;
        float hv = -INFINITY, gseg = 0.f, Cc = 0.f;
        if (s < 25 && endx > start) {
            gseg = s_slope[s];
            dir  = (gseg > 0.f) ? -1 : 1;
            hpos  = (dir > 0) ? start : endx - 1;
            hstop = (dir > 0) ? endx  : start - 1;
            horig = (int)s_uki[hpos];
            float u0 = s_uks[hpos];
            hv = eval4(bias, u0, s_co, lane);
            Cc = fmaf(-gseg, u0, hv);
        }
        unsigned fo = fmap(hv);

        // --- 32 pops (REDUX-only winner) + epilogue probe ---
        unsigned myvu = 0x80000000u; int myi = 0;   // fmap(0.0f)
#pragma unroll 1
        for (int it = 0; it < 32; it++) {
            unsigned vmx = __reduce_max_sync(FULLMASK, fo);
            unsigned ch = (fo == vmx) ? (unsigned)horig : 0xFFFFFFFFu;
            unsigned hmin = __reduce_min_sync(FULLMASK, ch);
            if (lane == it) { myvu = vmx; myi = (int)hmin; }
            if (fo == vmx && (unsigned)horig == hmin) {
                hpos += dir;
                if (hpos == hstop) { hv = -INFINITY; horig = 4095; }
                else { horig = (int)s_uki[hpos]; hv = fmaf(gseg, s_uks[hpos], Cc); }
                fo = fmap(hv);
            }
        }
        unsigned wv33u = __reduce_max_sync(FULLMASK, fo);
        float myv = funmap(myvu);

        unsigned minvu = __shfl_sync(FULLMASK, myvu, 31);
        if (wv33u == minvu) {
            if (minvu == 0x80000000u) {          // tied at exact 0.0f
                unsigned posmask = __ballot_sync(FULLMASK, myv > 0.0f);
                int c = __popc(posmask);
                float tbp = uq - s_p[23];
                float tbs = uq - s_p[0];
                int remaining = 32 - c, taken = 0, base = 0;
                while (remaining > 0 && base < L_DIM) {
                    float ukv = __ldg(gk + base + lane);
                    bool outw = (ukv <= tbp) || !(ukv <= tbs);
                    unsigned mask = __ballot_sync(FULLMASK, outw);
                    int cnt = __popc(mask);
                    int take = (cnt < remaining) ? cnt : remaining;
                    int slotpos = lane - (c + taken);
                    if (slotpos >= 0 && slotpos < take) {
                        int bitpos = (int)__fns(mask, 0, slotpos + 1);
                        myv = 0.0f; myi = base + bitpos;
                    }
                    taken += take; remaining -= take; base += 32;
                }
            } else {
                // nonzero boundary tie: exact streaming fallback
                float bestv; int besti; float curmin;
                {
                    bestv = eval4(bias, __ldg(gk + lane), s_co, lane);
                    besti = lane;
                    curmin = wmin(bestv);
                }
                for (int step = 1; step < 128; step++) {
                    int j = step * 32 + lane;
                    float cand = eval4(bias, __ldg(gk + j), s_co, lane);
                    unsigned mm = __ballot_sync(FULLMASK, cand > curmin);
                    while (mm) {
                        int src = __ffs(mm) - 1; mm &= mm - 1;
                        float cv = __shfl_sync(FULLMASK, cand, src);
                        if (cv > curmin) {
                            int cj = step * 32 + src;
                            float mv = bestv; int mi = besti; int ml = lane;
#pragma unroll
                            for (int off = 16; off > 0; off >>= 1) {
                                float ov = __shfl_xor_sync(FULLMASK, mv, off);
                                int oi = __shfl_xor_sync(FULLMASK, mi, off);
                                int ol = __shfl_xor_sync(FULLMASK, ml, off);
                                if (ov < mv || (ov == mv && oi > mi)) { mv = ov; mi = oi; ml = ol; }
                            }
                            if (lane == ml) { bestv = cv; besti = cj; }
                            curmin = wmin(bestv);
                        }
                    }
                }
                myv = bestv; myi = besti;
            }
        }

        // --- softmax + gather ---
        float rtau = d_rtau[b * L_DIM + q];
        float tv = myv * rtau;
        float mx = wmax(tv);
        float e = __expf(tv - mx);
        float se = wsum(e);
        float acc = 0.f;
#pragma unroll
        for (int k2 = 0; k2 < 32; k2++) {
            float ev = __shfl_sync(FULLMASK, e, k2);
            int ji = __shfl_sync(FULLMASK, myi, k2);
            acc = fmaf(ev, vp[(size_t)ji * 32 + lane], acc);
        }
        d_ctx[((size_t)b * L_DIM + q) * A_DIM + h * 32 + lane] = acc * (1.0f / se);
    }
}

// ---------------- K4: attn_out + LN2 + FFN -> v2 ----------------
__global__ void k4_ffn(const float* __restrict__ w_emb, const float* __restrict__ b_emb,
                       const float* __restrict__ ln2g, const float* __restrict__ ln2b,
                       const float* __restrict__ b1, const float* __restrict__ w_po,
                       const float* __restrict__ bpo) {
    __shared__ float sctx[8][4][A_DIM];
    __shared__ float sh2[8][4][A_DIM];
    int t = threadIdx.x, w = t >> 5, lane = t & 31;
    int tokbase = (blockIdx.x * 8 + w) * 4;

#pragma unroll
    for (int tt = 0; tt < 4; tt++)
#pragma unroll
        for (int m = 0; m < 3; m++)
            sctx[w][tt][lane + 32 * m] = d_ctx[(size_t)(tokbase + tt) * A_DIM + lane + 32 * m];
    __syncwarp();

    float ao[4][3];
#pragma unroll
    for (int tt = 0; tt < 4; tt++)
#pragma unroll
        for (int m = 0; m < 3; m++) ao[tt][m] = 0.f;
    for (int i = 0; i < A_DIM; i++) {
        float w0 = d_WoutT[i * A_DIM + lane];
        float w1 = d_WoutT[i * A_DIM + lane + 32];
        float w2 = d_WoutT[i * A_DIM + lane + 64];
#pragma unroll
        for (int tt = 0; tt < 4; tt++) {
            float cv = sctx[w][tt][i];
            ao[tt][0] = fmaf(cv, w0, ao[tt][0]);
            ao[tt][1] = fmaf(cv, w1, ao[tt][1]);
            ao[tt][2] = fmaf(cv, w2, ao[tt][2]);
        }
    }
    float we[3], be[3], g2[3], b2v[3], wp[3];
#pragma unroll
    for (int m = 0; m < 3; m++) {
        int a = lane + 32 * m;
        we[m] = w_emb[a]; be[m] = b_emb[a];
        g2[m] = ln2g[a];  b2v[m] = ln2b[a]; wp[m] = w_po[a];
    }
    float v2acc[4];
#pragma unroll
    for (int tt = 0; tt < 4; tt++) {
        float v0v = d_v0[tokbase + tt];
        float y0 = fmaf(v0v, we[0], be[0]) + ao[tt][0];
        float y1 = fmaf(v0v, we[1], be[1]) + ao[tt][1];
        float y2 = fmaf(v0v, we[2], be[2]) + ao[tt][2];
        v2acc[tt] = wsum(y0 * wp[0] + y1 * wp[1] + y2 * wp[2]);
        float s  = wsum(y0 + y1 + y2);
        float sq = wsum(y0 * y0 + y1 * y1 + y2 * y2);
        float mean = s * (1.0f / 96.0f);
        float var  = sq * (1.0f / 96.0f) - mean * mean;
        float rstd = rsqrtf(var + 1e-5f);
        sh2[w][tt][lane]      = fmaf((y0 - mean) * rstd, g2[0], b2v[0]);
        sh2[w][tt][lane + 32] = fmaf((y1 - mean) * rstd, g2[1], b2v[1]);
        sh2[w][tt][lane + 64] = fmaf((y2 - mean) * rstd, g2[2], b2v[2]);
    }
    __syncwarp();

    float acc[4][12];
#pragma unroll
    for (int tt = 0; tt < 4; tt++)
#pragma unroll
        for (int m = 0; m < 12; m++) acc[tt][m] = 0.f;
    for (int a = 0; a < A_DIM; a++) {
        float wv[12];
#pragma unroll
        for (int m = 0; m < 12; m++) wv[m] = d_W1T[a * 384 + lane + 32 * m];
#pragma unroll
        for (int tt = 0; tt < 4; tt++) {
            float hv = sh2[w][tt][a];
#pragma unroll
            for (int m = 0; m < 12; m++) acc[tt][m] = fmaf(hv, wv[m], acc[tt][m]);
        }
    }
    float b1v[12], w2v[12];
#pragma unroll
    for (int m = 0; m < 12; m++) {
        b1v[m] = b1[lane + 32 * m];
        w2v[m] = d_w2e[lane + 32 * m];
    }
    float bpo_v = bpo[0] + d_b2po[0];
#pragma unroll
    for (int tt = 0; tt < 4; tt++) {
        float fp = 0.f;
#pragma unroll
        for (int m = 0; m < 12; m++) {
            float xg = acc[tt][m] + b1v[m];
            float g = 0.5f * xg * (1.0f + erff(xg * 0.70710678118654752f));
            fp = fmaf(g, w2v[m], fp);
        }
        fp = wsum(fp);
        if (lane == 0) d_v2[tokbase + tt] = v2acc[tt] + bpo_v + fp;
    }
}

// ---------------- K5: out = LN(x + v2) over 4096 ----------------
__global__ void k5_final(const float* __restrict__ x, const float* __restrict__ lg,
                         const float* __restrict__ lb, float* __restrict__ out) {
    __shared__ float s_s[32], s_q[32];
    int b = blockIdx.x, t = threadIdx.x;
    float vals[4];
    float s = 0.f, sq = 0.f;
#pragma unroll
    for (int m = 0; m < 4; m++) {
        int i = t + 1024 * m;
        float v = x[b * L_DIM + i] + d_v2[b * L_DIM + i];
        vals[m] = v; s += v; sq += v * v;
    }
    s = wsum(s); sq = wsum(sq);
    int w = t >> 5, lane = t & 31;
    if (lane == 0) { s_s[w] = s; s_q[w] = sq; }
    __syncthreads();
    if (w == 0) {
        float a = s_s[lane], c = s_q[lane];
        a = wsum(a); c = wsum(c);
        if (lane == 0) { s_s[0] = a; s_q[0] = c; }
    }
    __syncthreads();
    float mean = s_s[0] * (1.0f / 4096.0f);
    float var  = s_q[0] * (1.0f / 4096.0f) - mean * mean;
    float rstd = rsqrtf(var + 1e-5f);
#pragma unroll
    for (int m = 0; m < 4; m++) {
        int i = t + 1024 * m;
        out[b * L_DIM + i] = fmaf((vals[m] - mean) * rstd, lg[i], lb[i]);
    }
}

extern "C" void kernel_launch(void* const* d_in, const int* in_sizes, int n_in,
                              void* d_out, int out_size) {
    const float* x       = (const float*)d_in[0];
    const float* W_pre   = (const float*)d_in[1];
    const float* b_pre   = (const float*)d_in[2];
    const float* w_emb   = (const float*)d_in[3];
    const float* b_emb   = (const float*)d_in[4];
    const float* ln1_g   = (const float*)d_in[5];
    const float* ln1_b   = (const float*)d_in[6];
    const float* Wq      = (const float*)d_in[7];
    const float* Wk      = (const float*)d_in[8];
    const float* Wv      = (const float*)d_in[9];
    const float* wq1     = (const float*)d_in[10];
    const float* wk1     = (const float*)d_in[11];
    const float* kcoeff  = (const float*)d_in[12];
    const float* tau_u   = (const float*)d_in[13];
    const float* tau_co  = (const float*)d_in[14];
    const float* Wout    = (const float*)d_in[15];
    const float* ln2_g   = (const float*)d_in[16];
    const float* ln2_b   = (const float*)d_in[17];
    const float* ffn_w1  = (const float*)d_in[18];
    const float* ffn_b1  = (const float*)d_in[19];
    const float* ffn_w2  = (const float*)d_in[20];
    const float* ffn_b2  = (const float*)d_in[21];
    const float* w_po    = (const float*)d_in[22];
    const float* b_po    = (const float*)d_in[23];
    const float* lnf_g   = (const float*)d_in[24];
    const float* lnf_b   = (const float*)d_in[25];
    float* out = (float*)d_out;

    k1_pre<<<528, 256>>>((const float4*)x, (const float4*)W_pre, b_pre,
                         Wq, Wk, wq1, wk1, ffn_w2, w_po, ffn_b2, Wout, ffn_w1, Wv);
    k2a_token<<<512, 256>>>(w_emb, b_emb, ln1_g, ln1_b, tau_u, tau_co);
    k2_sv<<<140, 1024>>>(w_emb, b_emb, ln1_g, ln1_b);
    k3_merge<<<dim3(MBLK, 12), 256>>>(kcoeff);
    k4_ffn<<<512, 256>>>(w_emb, b_emb, ln2_g, ln2_b, ffn_b1, w_po, b_po);
    k5_final<<<4, 1024>>>(x, lnf_g, lnf_b, out);
}